// round 16
// baseline (speedup 1.0000x reference)
#include <cuda_runtime.h>
#include <cuda_fp16.h>
#include <cstdint>
#include <cstddef>

#define BB 2
#define NN 2048
#define FF 32
#define DROWS 8192
#define DCOLS 2049
#define M1 6144
#define KO 2049
#define NTHR 256
#define THRS 0.086289726f
#define TOTC (BB*KO*FF)
#define FHCB 12589056   // M1*DCOLS halves per batch

#define SMA_SZ 18432u
#define SMB_OFF 55296u
#define SM_DYN 61440u
// gemmC (fp16 A): 3 stages of 128x80B + 3 B stages
#define SMA_C 10240u
#define SMB_C 30720u
#define SM_DYN_C 36864u

__device__ __align__(16) uint2 g_BxwI[BB*64*FF*8];
__device__ __align__(16) uint2 g_BxsI[BB*192*FF*8];
__device__ __align__(16) __half g_Fh[BB*FHCB];        // fp16 copy of d-crop (flat)
__device__ float g_pB[3*BB*FF*M1];
__device__ float g_part[8*TOTC];
__device__ unsigned g_cB[BB*48];
__device__ unsigned g_cC[BB*17];

__device__ __forceinline__ uint32_t packh(float lo, float hi){
    uint32_t r; asm("cvt.rn.f16x2.f32 %0, %1, %2;" : "=r"(r) : "f"(hi), "f"(lo)); return r;
}
__device__ __forceinline__ void mma_f16(float* c, uint32_t a0, uint32_t a1, uint32_t a2,
                                        uint32_t a3, uint32_t b0, uint32_t b1){
    asm("mma.sync.aligned.m16n8k16.row.col.f32.f16.f16.f32 "
        "{%0,%1,%2,%3},{%4,%5,%6,%7},{%8,%9},{%0,%1,%2,%3};"
        : "+f"(c[0]), "+f"(c[1]), "+f"(c[2]), "+f"(c[3])
        : "r"(a0), "r"(a1), "r"(a2), "r"(a3), "r"(b0), "r"(b1));
}
__device__ __forceinline__ void cpa16(uint32_t d, const void* s, int vs){
    asm volatile("cp.async.ca.shared.global [%0], [%1], 16, %2;" :: "r"(d), "l"(s), "r"(vs));
}
__device__ __forceinline__ void cpa_commit(){ asm volatile("cp.async.commit_group;"); }
template <int N> __device__ __forceinline__ void cpa_wait(){
    asm volatile("cp.async.wait_group %0;" :: "n"(N));
}
__device__ __forceinline__ int slot_of(int k2, int tg, int c){
    return (k2*4 + tg) ^ ((c & 2) << 1);
}

// ---------- kernel 1: xw = x@W -> fp16 interleaved ; fused col-0 patch ----------
__global__ __launch_bounds__(NTHR)
void k_xw(const float* __restrict__ x, const float* __restrict__ w,
          const float* __restrict__ dl){
    __shared__ float sx[32*33];
    __shared__ float sw[32*33];
    int tid = threadIdx.x;
    int b = blockIdx.x >> 6, j = blockIdx.x & 63;

    {
        int r = tid >> 3, q = tid & 7;
        const float* xs = x + ((size_t)b*NN + j*32)*FF;
        float4 xv = *(const float4*)(xs + r*FF + q*4);
        float4 wv = *(const float4*)(w + r*FF + q*4);
        sx[r*33 + q*4 + 0] = xv.x; sx[r*33 + q*4 + 1] = xv.y;
        sx[r*33 + q*4 + 2] = xv.z; sx[r*33 + q*4 + 3] = xv.w;
        sw[r*33 + q*4 + 0] = wv.x; sw[r*33 + q*4 + 1] = wv.y;
        sw[r*33 + q*4 + 2] = wv.z; sw[r*33 + q*4 + 3] = wv.w;
    }
    // fused: patch column 0 of the fp16 crop copy
    {
        int gt = blockIdx.x*NTHR + tid;
        if (gt < BB*M1){
            int b2 = gt / M1, m = gt % M1;
            g_Fh[(size_t)b2*FHCB + (size_t)m*DCOLS] =
                __float2half(dl[(size_t)b2*DROWS*DCOLS + (size_t)(2048+m)*DCOLS]);
        }
    }
    __syncthreads();

    int c = tid >> 3, s3 = tid & 7;
    int k2 = s3 >> 2, tg = s3 & 3;
    int n0 = k2*16 + 2*tg;
    float a0 = 0.f, a1 = 0.f, a2 = 0.f, a3 = 0.f;
#pragma unroll
    for (int f = 0; f < FF; f++){
        float wv = sw[f*33 + c];
        a0 = fmaf(sx[n0*33 + f],     wv, a0);
        a1 = fmaf(sx[(n0+1)*33 + f], wv, a1);
        a2 = fmaf(sx[(n0+8)*33 + f], wv, a2);
        a3 = fmaf(sx[(n0+9)*33 + f], wv, a3);
    }
    g_BxwI[(((size_t)b*64 + j)*FF + c)*8 + slot_of(k2, tg, c)] =
        make_uint2(packh(a0, a1), packh(a2, a3));
}

// ---------- gemmB: split-K=3, depth-3, fp16 writeback, fused eB ----------
__global__ __launch_bounds__(NTHR, 3)
void k_gemmB(const float* __restrict__ dl, const float* __restrict__ filt){
    extern __shared__ __align__(16) char sm[];
    uint32_t smb = (uint32_t)__cvta_generic_to_shared(sm);
    __shared__ int s_last;

    int tid = threadIdx.x, wid = tid>>5, lane = tid&31;
    int g = lane>>2, tg = lane&3;
    int bx = blockIdx.x;
    int b = bx / 144; int rem = bx % 144;
    int ksp = rem / 48, mtile = rem % 48, m0 = mtile * 128;
    int j0 = (ksp == 0) ? 0 : (ksp == 1 ? 22 : 43);
    int NCH = (ksp == 0) ? 22 : 21;

    const float* Ab = dl + (size_t)b*DROWS*DCOLS + (size_t)2048*DCOLS;
    const char* Bsrc = (const char*)g_BxwI + (size_t)b*131072;
    __half* Fh = g_Fh + (size_t)b*FHCB;

    auto prefetch = [&](int ch){
        int st = ch % 3;
        int j = j0 + ch, k0 = j*32;
#pragma unroll
        for (int j5 = 0; j5 < 5; j5++){
            int idx = tid + j5*NTHR;
            if (idx < 1152){
                int r = (idx*7282)>>16;
                int q = idx - r*9;
                int s = (r + 1) & 3;
                const float* src = Ab + (size_t)(m0+r)*DCOLS + (k0 + 1 - s) + q*4;
                int vs = (q < 8 || s) ? 16 : 0;
                cpa16(smb + st*SMA_SZ + (uint32_t)(r*144 + q*16), src, vs);
            }
        }
        if (tid < 128)
            cpa16(smb + SMB_OFF + st*2048u + (uint32_t)tid*16,
                  Bsrc + (size_t)j*2048 + tid*16, 16);
        cpa_commit();
    };

    float acc[4][4] = {};
    int r0 = 16*wid + g;
    int sft = (r0 + 1) & 3;

    prefetch(0); prefetch(1);
    for (int i = 0; i < NCH; i++){
        int st = i % 3;
        if (i < NCH-1) cpa_wait<1>(); else cpa_wait<0>();
        __syncthreads();
        if (i + 2 < NCH) prefetch(i + 2);

        const float* As = (const float*)(sm + st*SMA_SZ);
        const char* Bs = sm + SMB_OFF + st*2048u;
#pragma unroll
        for (int k2 = 0; k2 < 2; k2++){
            const float* p0 = As + r0*36 + sft + k2*16 + 2*tg;
            const float* p1 = p0 + 8*36;
            uint32_t a0 = packh(p0[0], p0[1]);
            uint32_t a2 = packh(p0[8], p0[9]);
            uint32_t a1 = packh(p1[0], p1[1]);
            uint32_t a3 = packh(p1[8], p1[9]);
#pragma unroll
            for (int nt = 0; nt < 4; nt++){
                int c = nt*8 + g;
                uint2 bb = *(const uint2*)(Bs + c*64 + slot_of(k2, tg, c)*8);
                mma_f16(acc[nt], a0, a1, a2, a3, bb.x, bb.y);
            }
        }
        // fp16 writeback of this A tile (coalesced 64B per row); stage st safe
        // until prefetch(i+3), which is behind the next __syncthreads.
        {
            size_t colbase = 1 + (size_t)(j0 + i)*32;
#pragma unroll
            for (int t = 0; t < 16; t++){
                int idx = tid + t*NTHR;
                int h = idx & 31, r = idx >> 5;
                int sf = (r + 1) & 3;
                float v = As[r*36 + sf + h];
                Fh[(size_t)(m0 + r)*DCOLS + colbase + h] = __float2half(v);
            }
        }
    }
    __syncthreads();

    float* sC = (float*)sm;
#pragma unroll
    for (int nt = 0; nt < 4; nt++){
        int cc = nt*8 + 2*tg;
        sC[cc*132 + r0]         = acc[nt][0];
        sC[(cc+1)*132 + r0]     = acc[nt][1];
        sC[cc*132 + r0 + 8]     = acc[nt][2];
        sC[(cc+1)*132 + r0 + 8] = acc[nt][3];
    }
    __syncthreads();
    {
        int c = tid >> 3, i8 = tid & 7;
        float* dst = g_pB + (((size_t)ksp*BB + b)*FF + c)*M1 + m0 + i8*16;
#pragma unroll
        for (int q = 0; q < 4; q++)
            *(float4*)(dst + q*4) = *(float4*)&sC[c*132 + i8*16 + q*4];
    }
    __threadfence();
    if (tid == 0){
        unsigned old = atomicAdd(&g_cB[b*48 + mtile], 1u);
        s_last = (old == 2u);
        if (old == 2u) g_cB[b*48 + mtile] = 0u;
    }
    __syncthreads();
    if (s_last){
#pragma unroll
        for (int t = 0; t < 4; t++){
            int oi = tid*4 + t;
            int jl = oi >> 8; int r8 = oi & 255;
            int c = r8 >> 3, s3 = r8 & 7;
            int k2 = s3 >> 2, tg2 = s3 & 3;
            int m = m0 + jl*32 + k2*16 + 2*tg2;
            float2 vlo = make_float2(0.f,0.f), vhi = make_float2(0.f,0.f);
#pragma unroll
            for (int s = 0; s < 3; s++){
                const float* p = g_pB + (((size_t)s*BB + b)*FF + c)*M1;
                float2 a = *(const float2*)(p + m);
                float2 h = *(const float2*)(p + m + 8);
                vlo.x += a.x; vlo.y += a.y; vhi.x += h.x; vhi.y += h.y;
            }
            float2 f0 = *(const float2*)(filt + 2048 + m);
            float2 f8 = *(const float2*)(filt + 2048 + m + 8);
            float t0 = vlo.x*f0.x, t1 = vlo.y*f0.y, t8 = vhi.x*f8.x, t9 = vhi.y*f8.y;
            if (m >= 2048){
                t0 = copysignf(fmaxf(fabsf(t0) - THRS, 0.f), t0);
                t1 = copysignf(fmaxf(fabsf(t1) - THRS, 0.f), t1);
                t8 = copysignf(fmaxf(fabsf(t8) - THRS, 0.f), t8);
                t9 = copysignf(fmaxf(fabsf(t9) - THRS, 0.f), t9);
            }
            int jg = (m0 >> 5) + jl;
            g_BxsI[(((size_t)b*192 + jg)*FF + c)*8 + slot_of(k2, tg2, c)] =
                make_uint2(packh(t0, t1), packh(t8, t9));
        }
    }
}

// ---------- gemmC: fp16 A from g_Fh; split-K=8, depth-3, fused combine ----------
__global__ __launch_bounds__(NTHR, 3)
void k_gemmC(const float* __restrict__ bias, float* __restrict__ out){
    extern __shared__ __align__(16) char sm[];
    uint32_t smb = (uint32_t)__cvta_generic_to_shared(sm);
    __shared__ int s_last;

    int tid = threadIdx.x, wid = tid>>5, lane = tid&31;
    int g = lane>>2, tg = lane&3;
    int bx = blockIdx.x;
    int b = bx / 136; int rem = bx % 136;
    int ksp = rem / 17, mtile = rem % 17, m0 = mtile * 128;
    const int NCH = 24;
    int j0 = ksp * 24;

    const __half* Fh = g_Fh + (size_t)b*FHCB;
    const char* Bsrc = (const char*)g_BxsI + (size_t)b*393216;

    auto prefetch = [&](int ch){
        int st = ch % 3;
        int jc = j0 + ch;
#pragma unroll
        for (int j2 = 0; j2 < 2; j2++){
            int idx = tid + j2*NTHR;           // 0..511
            int r = idx >> 2, q = idx & 3;
            int grow = m0 + r; if (grow >= KO) grow = 0;
            const __half* src = Fh + (size_t)grow*M1 + jc*32 + q*8;
            cpa16(smb + st*SMA_C + (uint32_t)(r*80 + q*16), src, 16);
        }
        if (tid < 128)
            cpa16(smb + SMB_C + st*2048u + (uint32_t)tid*16,
                  Bsrc + (size_t)jc*2048 + tid*16, 16);
        cpa_commit();
    };

    float acc[4][4] = {};
    int r0 = 16*wid + g;

    prefetch(0); prefetch(1);
    for (int i = 0; i < NCH; i++){
        int st = i % 3;
        if (i < NCH-1) cpa_wait<1>(); else cpa_wait<0>();
        __syncthreads();
        if (i + 2 < NCH) prefetch(i + 2);

        const char* As = sm + st*SMA_C;
        const char* Bs = sm + SMB_C + st*2048u;
#pragma unroll
        for (int k2 = 0; k2 < 2; k2++){
            const char* p0 = As + r0*80 + (k2*16 + 2*tg)*2;
            uint32_t a0 = *(const uint32_t*)(p0);
            uint32_t a2 = *(const uint32_t*)(p0 + 16);
            uint32_t a1 = *(const uint32_t*)(p0 + 8*80);
            uint32_t a3 = *(const uint32_t*)(p0 + 8*80 + 16);
#pragma unroll
            for (int nt = 0; nt < 4; nt++){
                int c = nt*8 + g;
                uint2 bb = *(const uint2*)(Bs + c*64 + slot_of(k2, tg, c)*8);
                mma_f16(acc[nt], a0, a1, a2, a3, bb.x, bb.y);
            }
        }
    }

    int g0 = m0 + r0, g1 = g0 + 8;
    float* base = g_part + (size_t)ksp*TOTC + (size_t)b*KO*FF;
#pragma unroll
    for (int nt = 0; nt < 4; nt++){
        int c0 = nt*8 + 2*tg;
        if (g0 < KO) *(float2*)(base + (size_t)g0*FF + c0) = make_float2(acc[nt][0], acc[nt][1]);
        if (g1 < KO) *(float2*)(base + (size_t)g1*FF + c0) = make_float2(acc[nt][2], acc[nt][3]);
    }
    __threadfence();
    if (tid == 0){
        unsigned old = atomicAdd(&g_cC[b*17 + mtile], 1u);
        s_last = (old == 7u);
        if (old == 7u) g_cC[b*17 + mtile] = 0u;
    }
    __syncthreads();
    if (s_last){
#pragma unroll
        for (int t = 0; t < 4; t++){
            int local = tid*16 + t*4;
            int row = local >> 5, c0 = local & 31;
            int grow = m0 + row;
            if (grow < KO){
                float4 s = *(const float4*)(bias + c0);
                size_t eo = ((size_t)b*KO + grow)*FF + c0;
#pragma unroll
                for (int sp = 0; sp < 8; sp++){
                    float4 p = *(const float4*)(g_part + (size_t)sp*TOTC + eo);
                    s.x += p.x; s.y += p.y; s.z += p.z; s.w += p.w;
                }
                *(float4*)(out + eo) = s;
            }
        }
    }
}

extern "C" void kernel_launch(void* const* d_in, const int* in_sizes, int n_in,
                              void* d_out, int out_size){
    (void)in_sizes; (void)n_in; (void)out_size;
    const float* x    = (const float*)d_in[0];
    const float* dl   = (const float*)d_in[1];
    const float* w    = (const float*)d_in[2];
    const float* filt = (const float*)d_in[3];
    const float* bias = (const float*)d_in[4];
    float* out = (float*)d_out;

    cudaFuncSetAttribute(k_gemmB, cudaFuncAttributeMaxDynamicSharedMemorySize, SM_DYN);
    cudaFuncSetAttribute(k_gemmC, cudaFuncAttributeMaxDynamicSharedMemorySize, SM_DYN_C);

    k_xw<<<BB*64, NTHR>>>(x, w, dl);
    k_gemmB<<<288, NTHR, SM_DYN>>>(dl, filt);
    k_gemmC<<<272, NTHR, SM_DYN_C>>>(bias, out);
}

// round 17
// speedup vs baseline: 1.3595x; 1.3595x over previous
#include <cuda_runtime.h>
#include <cuda_fp16.h>
#include <cstdint>
#include <cstddef>

#define BB 2
#define NN 2048
#define FF 32
#define DROWS 8192
#define DCOLS 2049
#define M1 6144
#define KO 2049
#define NTHR 256
#define THRS 0.086289726f
#define TOTC (BB*KO*FF)

#define SMA_SZ 18432u
#define SMB_OFF 73728u
#define SM_DYN 81920u

__device__ __align__(16) uint2 g_BxwI[BB*64*FF*8];    // xw fp16 interleaved
__device__ __align__(16) uint2 g_BxsI[BB*192*FF*8];   // x_shrink fp16 interleaved
__device__ float g_pB[3*BB*FF*M1];                    // gemmB partials [s][b][c][m]
__device__ float g_part[8*TOTC];                      // gemmC partials [s][b][g][c]
__device__ unsigned g_cB[BB*48];                      // gemmB tile counters
__device__ unsigned g_cC[BB*17];                      // gemmC tile counters

__device__ __forceinline__ uint32_t packh(float lo, float hi){
    uint32_t r; asm("cvt.rn.f16x2.f32 %0, %1, %2;" : "=r"(r) : "f"(hi), "f"(lo)); return r;
}
__device__ __forceinline__ void mma_f16(float* c, uint32_t a0, uint32_t a1, uint32_t a2,
                                        uint32_t a3, uint32_t b0, uint32_t b1){
    asm("mma.sync.aligned.m16n8k16.row.col.f32.f16.f16.f32 "
        "{%0,%1,%2,%3},{%4,%5,%6,%7},{%8,%9},{%0,%1,%2,%3};"
        : "+f"(c[0]), "+f"(c[1]), "+f"(c[2]), "+f"(c[3])
        : "r"(a0), "r"(a1), "r"(a2), "r"(a3), "r"(b0), "r"(b1));
}
__device__ __forceinline__ void cpa16(uint32_t d, const void* s, int vs){
    asm volatile("cp.async.ca.shared.global [%0], [%1], 16, %2;" :: "r"(d), "l"(s), "r"(vs));
}
__device__ __forceinline__ void cpa_commit(){ asm volatile("cp.async.commit_group;"); }
template <int N> __device__ __forceinline__ void cpa_wait(){
    asm volatile("cp.async.wait_group %0;" :: "n"(N));
}
__device__ __forceinline__ int slot_of(int k2, int tg, int c){
    return (k2*4 + tg) ^ ((c & 2) << 1);
}

// ---------- kernel 1: xw = x@W -> fp16 interleaved ----------
__global__ __launch_bounds__(NTHR)
void k_xw(const float* __restrict__ x, const float* __restrict__ w){
    __shared__ float sx[32*33];
    __shared__ float sw[32*33];
    int tid = threadIdx.x;
    int b = blockIdx.x >> 6, j = blockIdx.x & 63;
    {
        int r = tid >> 3, q = tid & 7;
        const float* xs = x + ((size_t)b*NN + j*32)*FF;
        float4 xv = *(const float4*)(xs + r*FF + q*4);
        float4 wv = *(const float4*)(w + r*FF + q*4);
        sx[r*33 + q*4 + 0] = xv.x; sx[r*33 + q*4 + 1] = xv.y;
        sx[r*33 + q*4 + 2] = xv.z; sx[r*33 + q*4 + 3] = xv.w;
        sw[r*33 + q*4 + 0] = wv.x; sw[r*33 + q*4 + 1] = wv.y;
        sw[r*33 + q*4 + 2] = wv.z; sw[r*33 + q*4 + 3] = wv.w;
    }
    __syncthreads();
    int c = tid >> 3, s3 = tid & 7;
    int k2 = s3 >> 2, tg = s3 & 3;
    int n0 = k2*16 + 2*tg;
    float a0 = 0.f, a1 = 0.f, a2 = 0.f, a3 = 0.f;
#pragma unroll
    for (int f = 0; f < FF; f++){
        float wv = sw[f*33 + c];
        a0 = fmaf(sx[n0*33 + f],     wv, a0);
        a1 = fmaf(sx[(n0+1)*33 + f], wv, a1);
        a2 = fmaf(sx[(n0+8)*33 + f], wv, a2);
        a3 = fmaf(sx[(n0+9)*33 + f], wv, a3);
    }
    g_BxwI[(((size_t)b*64 + j)*FF + c)*8 + slot_of(k2, tg, c)] =
        make_uint2(packh(a0, a1), packh(a2, a3));
}

// ---------- gemmB: split-K=3, depth-4 pipeline, fused eB finisher ----------
__global__ __launch_bounds__(NTHR, 2)
void k_gemmB(const float* __restrict__ dl, const float* __restrict__ filt){
    extern __shared__ __align__(16) char sm[];
    uint32_t smb = (uint32_t)__cvta_generic_to_shared(sm);
    __shared__ int s_last;

    int tid = threadIdx.x, wid = tid>>5, lane = tid&31;
    int g = lane>>2, tg = lane&3;
    int bx = blockIdx.x;
    int b = bx / 144; int rem = bx % 144;
    int ksp = rem / 48, mtile = rem % 48, m0 = mtile * 128;
    int j0 = (ksp == 0) ? 0 : (ksp == 1 ? 22 : 43);
    int NCH = (ksp == 0) ? 22 : 21;

    const float* Ab = dl + (size_t)b*DROWS*DCOLS + (size_t)2048*DCOLS;
    const char* Bsrc = (const char*)g_BxwI + (size_t)b*131072;

    auto prefetch = [&](int ch){
        int st = ch & 3;
        int j = j0 + ch, k0 = j*32;
#pragma unroll
        for (int j5 = 0; j5 < 5; j5++){
            int idx = tid + j5*NTHR;
            if (idx < 1152){
                int r = (idx*7282)>>16;
                int q = idx - r*9;
                int s = (r + 1) & 3;
                const float* src = Ab + (size_t)(m0+r)*DCOLS + (k0 + 1 - s) + q*4;
                int vs = (q < 8 || s) ? 16 : 0;
                cpa16(smb + st*SMA_SZ + (uint32_t)(r*144 + q*16), src, vs);
            }
        }
        if (tid < 128)
            cpa16(smb + SMB_OFF + st*2048u + (uint32_t)tid*16,
                  Bsrc + (size_t)j*2048 + tid*16, 16);
        cpa_commit();
    };

    float acc[4][4] = {};
    int r0 = 16*wid + g;
    int sft = (r0 + 1) & 3;

    prefetch(0); prefetch(1); prefetch(2);
    for (int i = 0; i < NCH; i++){
        int st = i & 3;
        int ahead = NCH - 1 - i;
        if (ahead >= 2) cpa_wait<2>();
        else if (ahead == 1) cpa_wait<1>();
        else cpa_wait<0>();
        __syncthreads();
        if (i + 3 < NCH) prefetch(i + 3);

        const float* As = (const float*)(sm + st*SMA_SZ);
        const char* Bs = sm + SMB_OFF + st*2048u;
#pragma unroll
        for (int k2 = 0; k2 < 2; k2++){
            const float* p0 = As + r0*36 + sft + k2*16 + 2*tg;
            const float* p1 = p0 + 8*36;
            uint32_t a0 = packh(p0[0], p0[1]);
            uint32_t a2 = packh(p0[8], p0[9]);
            uint32_t a1 = packh(p1[0], p1[1]);
            uint32_t a3 = packh(p1[8], p1[9]);
#pragma unroll
            for (int nt = 0; nt < 4; nt++){
                int c = nt*8 + g;
                uint2 bb = *(const uint2*)(Bs + c*64 + slot_of(k2, tg, c)*8);
                mma_f16(acc[nt], a0, a1, a2, a3, bb.x, bb.y);
            }
        }
    }
    __syncthreads();

    // epilogue -> partials [ksp][b][c][m]
    float* sC = (float*)sm;
#pragma unroll
    for (int nt = 0; nt < 4; nt++){
        int cc = nt*8 + 2*tg;
        sC[cc*132 + r0]         = acc[nt][0];
        sC[(cc+1)*132 + r0]     = acc[nt][1];
        sC[cc*132 + r0 + 8]     = acc[nt][2];
        sC[(cc+1)*132 + r0 + 8] = acc[nt][3];
    }
    __syncthreads();
    {
        int c = tid >> 3, i8 = tid & 7;
        float* dst = g_pB + (((size_t)ksp*BB + b)*FF + c)*M1 + m0 + i8*16;
#pragma unroll
        for (int q = 0; q < 4; q++)
            *(float4*)(dst + q*4) = *(float4*)&sC[c*132 + i8*16 + q*4];
    }
    __threadfence();
    if (tid == 0){
        unsigned old = atomicAdd(&g_cB[b*48 + mtile], 1u);
        s_last = (old == 2u);
        if (old == 2u) g_cB[b*48 + mtile] = 0u;
    }
    __syncthreads();
    if (s_last){
#pragma unroll
        for (int t = 0; t < 4; t++){
            int oi = tid*4 + t;
            int jl = oi >> 8; int r8 = oi & 255;
            int c = r8 >> 3, s3 = r8 & 7;
            int k2 = s3 >> 2, tg2 = s3 & 3;
            int m = m0 + jl*32 + k2*16 + 2*tg2;
            float2 vlo = make_float2(0.f,0.f), vhi = make_float2(0.f,0.f);
#pragma unroll
            for (int s = 0; s < 3; s++){
                const float* p = g_pB + (((size_t)s*BB + b)*FF + c)*M1;
                float2 a = *(const float2*)(p + m);
                float2 h = *(const float2*)(p + m + 8);
                vlo.x += a.x; vlo.y += a.y; vhi.x += h.x; vhi.y += h.y;
            }
            float2 f0 = *(const float2*)(filt + 2048 + m);
            float2 f8 = *(const float2*)(filt + 2048 + m + 8);
            float t0 = vlo.x*f0.x, t1 = vlo.y*f0.y, t8 = vhi.x*f8.x, t9 = vhi.y*f8.y;
            if (m >= 2048){
                t0 = copysignf(fmaxf(fabsf(t0) - THRS, 0.f), t0);
                t1 = copysignf(fmaxf(fabsf(t1) - THRS, 0.f), t1);
                t8 = copysignf(fmaxf(fabsf(t8) - THRS, 0.f), t8);
                t9 = copysignf(fmaxf(fabsf(t9) - THRS, 0.f), t9);
            }
            int jg = (m0 >> 5) + jl;
            g_BxsI[(((size_t)b*192 + jg)*FF + c)*8 + slot_of(k2, tg2, c)] =
                make_uint2(packh(t0, t1), packh(t8, t9));
        }
    }
}

// ---------- gemmC: split-K=8, depth-4 pipeline, fused combine finisher ----------
__global__ __launch_bounds__(NTHR, 2)
void k_gemmC(const float* __restrict__ dl, const float* __restrict__ bias,
             float* __restrict__ out){
    extern __shared__ __align__(16) char sm[];
    uint32_t smb = (uint32_t)__cvta_generic_to_shared(sm);
    __shared__ int s_last;

    int tid = threadIdx.x, wid = tid>>5, lane = tid&31;
    int g = lane>>2, tg = lane&3;
    int bx = blockIdx.x;
    int b = bx / 136; int rem = bx % 136;
    int ksp = rem / 17, mtile = rem % 17, m0 = mtile * 128;
    const int NCH = 24;
    int j0 = ksp * 24;

    const float* crop = dl + (size_t)b*DROWS*DCOLS + (size_t)2048*DCOLS;
    const char* Bsrc = (const char*)g_BxsI + (size_t)b*393216;

    auto prefetch = [&](int ch){
        int st = ch & 3;
        int jc = j0 + ch;
#pragma unroll
        for (int j4 = 0; j4 < 4; j4++){
            int idx = tid + j4*NTHR;
            int r = idx >> 3, q = idx & 7;
            int grow = m0 + r; if (grow >= KO) grow = 0;
            const float* src = crop + (size_t)grow*M1 + jc*32 + q*4;
            cpa16(smb + st*SMA_SZ + (uint32_t)(r*144 + q*16), src, 16);
        }
        if (tid < 128)
            cpa16(smb + SMB_OFF + st*2048u + (uint32_t)tid*16,
                  Bsrc + (size_t)jc*2048 + tid*16, 16);
        cpa_commit();
    };

    float acc[4][4] = {};
    int r0 = 16*wid + g;

    prefetch(0); prefetch(1); prefetch(2);
    for (int i = 0; i < NCH; i++){
        int st = i & 3;
        int ahead = NCH - 1 - i;
        if (ahead >= 2) cpa_wait<2>();
        else if (ahead == 1) cpa_wait<1>();
        else cpa_wait<0>();
        __syncthreads();
        if (i + 3 < NCH) prefetch(i + 3);

        const float* As = (const float*)(sm + st*SMA_SZ);
        const char* Bs = sm + SMB_OFF + st*2048u;
#pragma unroll
        for (int k2 = 0; k2 < 2; k2++){
            const float* p0 = As + r0*36 + k2*16 + 2*tg;
            const float* p1 = p0 + 8*36;
            uint32_t a0 = packh(p0[0], p0[1]);
            uint32_t a2 = packh(p0[8], p0[9]);
            uint32_t a1 = packh(p1[0], p1[1]);
            uint32_t a3 = packh(p1[8], p1[9]);
#pragma unroll
            for (int nt = 0; nt < 4; nt++){
                int c = nt*8 + g;
                uint2 bb = *(const uint2*)(Bs + c*64 + slot_of(k2, tg, c)*8);
                mma_f16(acc[nt], a0, a1, a2, a3, bb.x, bb.y);
            }
        }
    }

    int g0 = m0 + r0, g1 = g0 + 8;
    float* base = g_part + (size_t)ksp*TOTC + (size_t)b*KO*FF;
#pragma unroll
    for (int nt = 0; nt < 4; nt++){
        int c0 = nt*8 + 2*tg;
        if (g0 < KO) *(float2*)(base + (size_t)g0*FF + c0) = make_float2(acc[nt][0], acc[nt][1]);
        if (g1 < KO) *(float2*)(base + (size_t)g1*FF + c0) = make_float2(acc[nt][2], acc[nt][3]);
    }
    __threadfence();
    if (tid == 0){
        unsigned old = atomicAdd(&g_cC[b*17 + mtile], 1u);
        s_last = (old == 7u);
        if (old == 7u) g_cC[b*17 + mtile] = 0u;
    }
    __syncthreads();
    if (s_last){
#pragma unroll
        for (int t = 0; t < 4; t++){
            int local = tid*16 + t*4;
            int row = local >> 5, c0 = local & 31;
            int grow = m0 + row;
            if (grow < KO){
                float4 s = *(const float4*)(bias + c0);
                size_t eo = ((size_t)b*KO + grow)*FF + c0;
#pragma unroll
                for (int sp = 0; sp < 8; sp++){
                    float4 p = *(const float4*)(g_part + (size_t)sp*TOTC + eo);
                    s.x += p.x; s.y += p.y; s.z += p.z; s.w += p.w;
                }
                *(float4*)(out + eo) = s;
            }
        }
    }
}

extern "C" void kernel_launch(void* const* d_in, const int* in_sizes, int n_in,
                              void* d_out, int out_size){
    (void)in_sizes; (void)n_in; (void)out_size;
    const float* x    = (const float*)d_in[0];
    const float* dl   = (const float*)d_in[1];
    const float* w    = (const float*)d_in[2];
    const float* filt = (const float*)d_in[3];
    const float* bias = (const float*)d_in[4];
    float* out = (float*)d_out;

    cudaFuncSetAttribute(k_gemmB, cudaFuncAttributeMaxDynamicSharedMemorySize, SM_DYN);
    cudaFuncSetAttribute(k_gemmC, cudaFuncAttributeMaxDynamicSharedMemorySize, SM_DYN);

    k_xw<<<BB*64, NTHR>>>(x, w);
    k_gemmB<<<288, NTHR, SM_DYN>>>(dl, filt);
    k_gemmC<<<272, NTHR, SM_DYN>>>(dl, bias, out);
}